// round 15
// baseline (speedup 1.0000x reference)
#include <cuda_runtime.h>
#include <cuda_bf16.h>
#include <math.h>
#include <math_constants.h>
#include <stdint.h>

// Problem dims
#define Nn 16
#define Ss 64
#define Hh 256
#define FAa 256
#define Bb (Nn*Ss)              // 1024 chains / rows
#define NM_ELEMS (Nn*Ss*Hh)     // 262144
#define ATTN_ELEMS (Nn*Ss*Ss)   // 65536
#define STEP_CTAS 128

// Scratch (device globals: no allocation allowed)
__device__ float g_A1[Bb*Hh];
__device__ float g_A2[Bb*Hh];
__device__ float g_Ca[Bb*Hh];
__device__ float g_Cb[Bb*Hh];
__device__ float g_aT[Ss*Bb];               // attn transposed: [t][b]
__device__ __nv_bfloat16 g_Whi[256*1024];   // z1w split hi
__device__ __nv_bfloat16 g_Wlo[256*1024];   // z1w split lo

// ---------------------------------------------------------------------------
// Helpers
// ---------------------------------------------------------------------------
__device__ __forceinline__ float fast_tanh(float x)
{
    float e = __expf(2.0f * x);
    return 1.0f - __fdividef(2.0f, e + 1.0f);
}
__device__ __forceinline__ float fast_sigmoid(float x)
{
    float e = __expf(-x);
    return __fdividef(1.0f, 1.0f + e);
}

// ---- packed fp32x2 (B300 FFMA2) ----
__device__ __forceinline__ uint64_t packf2(float x)
{
    uint64_t r;
    uint32_t u = __float_as_uint(x);
    asm("mov.b64 %0, {%1, %1};" : "=l"(r) : "r"(u));
    return r;
}
__device__ __forceinline__ void fma2(uint64_t& d, uint64_t a, uint64_t b)
{
    asm("fma.rn.f32x2 %0, %1, %2, %0;" : "+l"(d) : "l"(a), "l"(b));
}
__device__ __forceinline__ void add2(uint64_t& d, uint64_t a)
{
    asm("add.rn.f32x2 %0, %0, %1;" : "+l"(d) : "l"(a));
}
__device__ __forceinline__ float2 unpackf2(uint64_t v)
{
    float2 f;
    asm("mov.b64 {%0, %1}, %2;" : "=f"(f.x), "=f"(f.y) : "l"(v));
    return f;
}

// Pack two floats to bf16x2 and residual pack.
__device__ __forceinline__ uint32_t split2(float x, float y, uint32_t& lo)
{
    uint32_t hi;
    asm("cvt.rn.bf16x2.f32 %0, %1, %2;" : "=r"(hi) : "f"(y), "f"(x));
    float xr = x - __uint_as_float(hi << 16);
    float yr = y - __uint_as_float(hi & 0xffff0000u);
    asm("cvt.rn.bf16x2.f32 %0, %1, %2;" : "=r"(lo) : "f"(yr), "f"(xr));
    return hi;
}

__device__ __forceinline__ void mma_bf16(float* d, const uint32_t* a,
                                         uint32_t b0, uint32_t b1)
{
    asm volatile(
        "mma.sync.aligned.m16n8k16.row.col.f32.bf16.bf16.f32 "
        "{%0,%1,%2,%3}, {%4,%5,%6,%7}, {%8,%9}, {%0,%1,%2,%3};"
        : "+f"(d[0]), "+f"(d[1]), "+f"(d[2]), "+f"(d[3])
        : "r"(a[0]), "r"(a[1]), "r"(a[2]), "r"(a[3]), "r"(b0), "r"(b1));
}

__device__ __forceinline__ void ldm_x4(uint32_t* r, uint32_t addr)
{
    asm volatile("ldmatrix.sync.aligned.m8n8.x4.shared.b16 {%0,%1,%2,%3}, [%4];"
        : "=r"(r[0]), "=r"(r[1]), "=r"(r[2]), "=r"(r[3]) : "r"(addr));
}

__device__ __forceinline__ void cp16(uint32_t dst, const void* src)
{
    asm volatile("cp.async.cg.shared.global [%0], [%1], 16;" :: "r"(dst), "l"(src));
}

// ---------------------------------------------------------------------------
// Pre-split z1w into bf16 hi/lo
// ---------------------------------------------------------------------------
__global__ void splitw_kernel(const float* __restrict__ z1w) {
    int i = blockIdx.x * 256 + threadIdx.x;
    #pragma unroll
    for (int e = 0; e < 4; e++) {
        int idx = e * 65536 + i;
        float w = z1w[idx];
        __nv_bfloat16 h = __float2bfloat16_rn(w);
        g_Whi[idx] = h;
        g_Wlo[idx] = __float2bfloat16_rn(w - __bfloat162float(h));
    }
}

// ---------------------------------------------------------------------------
// A1/A2 precompute + fused zero of Ca.
// ---------------------------------------------------------------------------
__global__ void a12_kernel(const float* __restrict__ facts,
                           const float* __restrict__ Wr, const float* __restrict__ Wrb,
                           const float* __restrict__ Urb,
                           const float* __restrict__ W,  const float* __restrict__ Wb)
{
    __shared__ float sX[64*68];
    __shared__ float sWm[64*68];
    const int rt = blockIdx.x;
    const int yy = blockIdx.y;
    const bool first = (yy < 4);
    const int ot = first ? yy : yy - 4;
    const float* Wm = first ? Wr : W;
    float* outp = first ? g_A1 : g_A2;

    const int tid = threadIdx.x;
    const int bid = blockIdx.y * 16 + blockIdx.x;   // 0..127

    #pragma unroll
    for (int e = 0; e < 8; e++)
        g_Ca[bid*2048 + e*256 + tid] = 0.0f;

    const int tr = tid & 15, to = tid >> 4;
    const int r0 = tr*4, o0 = to*4;
    uint64_t accp[4][2];
    #pragma unroll
    for (int a = 0; a < 4; a++) { accp[a][0] = 0ull; accp[a][1] = 0ull; }

    for (int k0 = 0; k0 < 256; k0 += 64) {
        __syncthreads();
        #pragma unroll
        for (int e = 0; e < 16; e++) {
            int idx = e*256 + tid;
            int r = idx >> 6, k = idx & 63;
            sX[k*68 + r]  = facts[(size_t)(rt*64 + r)*256 + k0 + k];
            int o = r;
            sWm[k*68 + o] = Wm[(size_t)(ot*64 + o)*256 + k0 + k];
        }
        __syncthreads();
        #pragma unroll 4
        for (int k = 0; k < 64; k++) {
            float4 xv = *(const float4*)&sX[k*68 + r0];
            uint64_t w01 = *(const uint64_t*)&sWm[k*68 + o0];
            uint64_t w23 = *(const uint64_t*)&sWm[k*68 + o0 + 2];
            uint64_t p0 = packf2(xv.x), p1 = packf2(xv.y);
            uint64_t p2 = packf2(xv.z), p3 = packf2(xv.w);
            fma2(accp[0][0], p0, w01); fma2(accp[0][1], p0, w23);
            fma2(accp[1][0], p1, w01); fma2(accp[1][1], p1, w23);
            fma2(accp[2][0], p2, w01); fma2(accp[2][1], p2, w23);
            fma2(accp[3][0], p3, w01); fma2(accp[3][1], p3, w23);
        }
    }
    #pragma unroll
    for (int rr = 0; rr < 4; rr++) {
        float2 lo = unpackf2(accp[rr][0]);
        float2 hi = unpackf2(accp[rr][1]);
        float vals[4] = {lo.x, lo.y, hi.x, hi.y};
        #pragma unroll
        for (int oo = 0; oo < 4; oo++) {
            int o = ot*64 + o0 + oo;
            float bias = first ? (Wrb[o] + Urb[o]) : Wb[o];
            outp[(size_t)(rt*64 + r0 + rr)*256 + o] = vals[oo] + bias;
        }
    }
}

// ---------------------------------------------------------------------------
// Gate MLP via bf16-split mma.sync + fused masked softmax (attn + attnT).
// ---------------------------------------------------------------------------
#define SFP     268
#define WOFF    0
#define WBUFSZ  73728
#define WHALF   36864
#define SFOFF   147456
#define QOFF    (SFOFF + 68608)
#define B1OFF   (QOFF + 4096)
#define Z2OFF   (B1OFF + 1024)
#define REDOFF  (Z2OFF + 1024)
#define SGOFF   (REDOFF + 8192)
#define GATE_SMEM_BYTES (SGOFF + 512)

__global__ void __launch_bounds__(512, 1)
gate_kernel(const float* __restrict__ facts,
            const float* __restrict__ prevM,
            const float* __restrict__ questions,
            const float* __restrict__ z1b,
            const float* __restrict__ z2w,
            const float* __restrict__ z2b,
            const int* __restrict__ doc_len,
            float* __restrict__ out_attn)
{
    extern __shared__ char smc[];
    float* sf  = (float*)(smc + SFOFF);
    float* sQ0 = (float*)(smc + QOFF);
    float* sQ1 = sQ0 + 256;
    float* sM0 = sQ1 + 256;
    float* sM1 = sM0 + 256;
    float* sb1 = (float*)(smc + B1OFF);
    float* sz2 = (float*)(smc + Z2OFF);
    float* red = (float*)(smc + REDOFF);
    float* sG  = (float*)(smc + SGOFF);
    const uint32_t smbase = (uint32_t)__cvta_generic_to_shared(smc);

    const int tid  = threadIdx.x;
    const int lane = tid & 31;
    const int wid  = tid >> 5;
    const int g    = lane >> 2;
    const int tg   = lane & 3;
    const int wm   = wid & 3;
    const int wn   = wid >> 2;

    const int bx  = blockIdx.x;
    const int n   = bx >> 5;
    const int ip  = bx & 31;
    const int ni0 = n*64 + ip*2;

    {
        const float2* f2 = (const float2*)(facts + (size_t)n * Ss * Hh);
        #pragma unroll
        for (int e = 0; e < 16; e++) {
            int idx = e*512 + tid;
            int j = idx >> 7, h2 = idx & 127;
            *(float2*)&sf[j*SFP + h2*2] = f2[idx];
        }
        if (tid < 256) {
            sQ0[tid] = questions[(size_t)ni0*256 + tid];
            sQ1[tid] = questions[(size_t)(ni0+1)*256 + tid];
            sM0[tid] = prevM[(size_t)ni0*256 + tid];
            sM1[tid] = prevM[(size_t)(ni0+1)*256 + tid];
            sb1[tid] = z1b[tid];
            sz2[tid] = z2w[tid];
        }
    }

    const int wrow  = tid >> 1;
    const int whalf = tid & 1;

    {
        const char* gh = (const char*)(g_Whi + (size_t)wrow*1024 + whalf*32);
        const char* gl = (const char*)(g_Wlo + (size_t)wrow*1024 + whalf*32);
        uint32_t dh = smbase + WOFF + (uint32_t)(wrow*144 + whalf*64);
        uint32_t dl = dh + WHALF;
        #pragma unroll
        for (int u = 0; u < 4; u++) { cp16(dh + u*16, gh + u*16); cp16(dl + u*16, gl + u*16); }
        asm volatile("cp.async.commit_group;");
        asm volatile("cp.async.wait_group 0;");
    }
    __syncthreads();

    float acc[2][8][4];
    #pragma unroll
    for (int mt = 0; mt < 2; mt++)
        #pragma unroll
        for (int nt = 0; nt < 8; nt++)
            #pragma unroll
            for (int v = 0; v < 4; v++) acc[mt][nt][v] = 0.0f;

    const uint32_t broff = (uint32_t)((wn*64 + ((lane>>4)&1)*8 + (lane&7)) * 144
                                      + ((lane>>3)&1)*16);

    for (int c = 0; c < 16; c++) {
        if (c < 15) {
            const char* gh = (const char*)(g_Whi + (size_t)wrow*1024 + (c+1)*64 + whalf*32);
            const char* gl = (const char*)(g_Wlo + (size_t)wrow*1024 + (c+1)*64 + whalf*32);
            uint32_t dh = smbase + WOFF + (uint32_t)(((c+1)&1)*WBUFSZ)
                        + (uint32_t)(wrow*144 + whalf*64);
            uint32_t dl = dh + WHALF;
            #pragma unroll
            for (int u = 0; u < 4; u++) { cp16(dh + u*16, gh + u*16); cp16(dl + u*16, gl + u*16); }
            asm volatile("cp.async.commit_group;");
        }

        const int  bterm = c >> 2;
        const int  h0    = (c & 3) * 64;
        const bool isabs = (bterm >= 2);
        const uint32_t wbase = smbase + WOFF + (uint32_t)((c&1)*WBUFSZ);

        #pragma unroll
        for (int ks = 0; ks < 4; ks++) {
            const int h = h0 + ks*16;

            uint32_t Ah[2][4], Al[2][4];
            #pragma unroll
            for (int mt = 0; mt < 2; mt++) {
                const int rb   = wm*32 + mt*16 + g;
                const int isel = rb >> 6;
                const float* tv = (bterm & 1) ? (isel ? sM1 : sM0)
                                              : (isel ? sQ1 : sQ0);
                const int j0 = rb & 63;
                const float* fr0 = &sf[j0*SFP + h + tg*2];
                const float* fr1 = fr0 + 8*SFP;
                float2 t0  = *(const float2*)&tv[h + tg*2];
                float2 t1  = *(const float2*)&tv[h + tg*2 + 8];
                float2 fa  = *(const float2*)fr0;
                float2 fA  = *(const float2*)(fr0 + 8);
                float2 fb  = *(const float2*)fr1;
                float2 fB  = *(const float2*)(fr1 + 8);
                float z00, z01, z10, z11, z20, z21, z30, z31;
                if (isabs) {
                    z00 = fabsf(fa.x - t0.x); z01 = fabsf(fa.y - t0.y);
                    z10 = fabsf(fb.x - t0.x); z11 = fabsf(fb.y - t0.y);
                    z20 = fabsf(fA.x - t1.x); z21 = fabsf(fA.y - t1.y);
                    z30 = fabsf(fB.x - t1.x); z31 = fabsf(fB.y - t1.y);
                } else {
                    z00 = fa.x * t0.x; z01 = fa.y * t0.y;
                    z10 = fb.x * t0.x; z11 = fb.y * t0.y;
                    z20 = fA.x * t1.x; z21 = fA.y * t1.y;
                    z30 = fB.x * t1.x; z31 = fB.y * t1.y;
                }
                Ah[mt][0] = split2(z00, z01, Al[mt][0]);
                Ah[mt][1] = split2(z10, z11, Al[mt][1]);
                Ah[mt][2] = split2(z20, z21, Al[mt][2]);
                Ah[mt][3] = split2(z30, z31, Al[mt][3]);
            }

            #pragma unroll
            for (int pass = 0; pass < 3; pass++) {
                const uint32_t* A0 = (pass == 1) ? Al[0] : Ah[0];
                const uint32_t* A1 = (pass == 1) ? Al[1] : Ah[1];
                const uint32_t hoff = (pass == 2) ? (uint32_t)WHALF : 0u;
                #pragma unroll
                for (int p = 0; p < 4; p++) {
                    uint32_t bfr[4];
                    ldm_x4(bfr, wbase + broff + (uint32_t)(p*16*144 + ks*32) + hoff);
                    mma_bf16(acc[0][p*2],   A0, bfr[0], bfr[1]);
                    mma_bf16(acc[1][p*2],   A1, bfr[0], bfr[1]);
                    mma_bf16(acc[0][p*2+1], A0, bfr[2], bfr[3]);
                    mma_bf16(acc[1][p*2+1], A1, bfr[2], bfr[3]);
                }
            }
        }

        if (c < 15) asm volatile("cp.async.wait_group 0;");
        __syncthreads();
    }

    #pragma unroll
    for (int mt = 0; mt < 2; mt++) {
        #pragma unroll
        for (int rh = 0; rh < 2; rh++) {
            const int r = wm*32 + mt*16 + rh*8 + g;
            float s = 0.0f;
            #pragma unroll
            for (int nt = 0; nt < 8; nt++) {
                #pragma unroll
                for (int cc = 0; cc < 2; cc++) {
                    const int a = wn*64 + nt*8 + tg*2 + cc;
                    float x = acc[mt][nt][rh*2 + cc] + sb1[a];
                    s += fast_tanh(x) * sz2[a];
                }
            }
            red[r*16 + wn*4 + tg] = s;
        }
    }
    __syncthreads();
    if (tid < 128) {
        float G = z2b[0];
        #pragma unroll
        for (int u = 0; u < 16; u++) G += red[tid*16 + u];
        sG[tid] = G;
    }
    __syncthreads();
    if (wid < 2) {
        const int row = wid;
        const int dl  = doc_len[n];
        const int b   = ni0 + row;
        float v0 = sG[row*64 + lane];
        float v1 = sG[row*64 + 32 + lane];
        float x0 = (lane      < dl && v0 != 0.0f) ? v0 : -CUDART_INF_F;
        float x1 = (lane + 32 < dl && v1 != 0.0f) ? v1 : -CUDART_INF_F;
        float mx = fmaxf(x0, x1);
        #pragma unroll
        for (int o = 16; o >= 1; o >>= 1)
            mx = fmaxf(mx, __shfl_xor_sync(0xffffffffu, mx, o));
        float e0 = expf(x0 - mx);
        float e1 = expf(x1 - mx);
        float s = e0 + e1;
        #pragma unroll
        for (int o = 16; o >= 1; o >>= 1)
            s += __shfl_xor_sync(0xffffffffu, s, o);
        float inv = 1.0f / s;
        float a0 = e0 * inv, a1 = e1 * inv;
        out_attn[b*64 + lane]      = a0;
        out_attn[b*64 + 32 + lane] = a1;
        g_aT[lane*1024 + b]        = a0;
        g_aT[(lane+32)*1024 + b]   = a1;
    }
}

// ---------------------------------------------------------------------------
// Persistent GRU, split-K, CLUSTERED: 16 clusters of 8 CTAs (one chain-tile
// per cluster). Inter-step sync = barrier.cluster (~0.4k cyc) instead of the
// gmem grid barrier. Own 32-out slice kept in smem across steps (staging
// skips it after t=0).
// ---------------------------------------------------------------------------
#define WP 40
#define CP 66
#define GRED_U64 (8*256)
#define GRU_SMEM_BYTES ((2*256*WP + 256*CP)*4 + GRED_U64*8)  // 165888

__global__ void __launch_bounds__(512, 1) __cluster_dims__(8, 1, 1)
gru_persistent(float* __restrict__ Ca, float* __restrict__ Cb,
               const float* __restrict__ Ur, const float* __restrict__ U,
               const float* __restrict__ Ub)
{
    extern __shared__ float smem[];
    float* sUr = smem;                      // 256 x 40 (k x o)
    float* sU  = sUr + 256*WP;
    float* sC  = sU  + 256*WP;              // 256 x 66 (k x chain)
    uint64_t* red64 = (uint64_t*)(sC + 256*CP);   // 8 x 256

    const int bx  = blockIdx.x;
    const int ct  = bx >> 3;                // chain tile (16), 64 chains
    const int ot  = bx & 7;                 // out tile (8), 32 outs
    const int tid = threadIdx.x;
    const int rid = tid & 255;
    const int khalf = tid >> 8;             // 0: k<128, 1: k>=128
    const int c0  = (rid & 31) * 2;         // 2 chains
    const int o0  = (rid >> 5) * 4;         // 4 outs
    const int o_0 = ot*32 + o0;
    const int kbase = khalf * 128;

    // Load weight slices once (512 threads)
    #pragma unroll
    for (int e = 0; e < 16; e++) {
        int idx = e*512 + tid;
        int o = idx >> 8, k = idx & 255;
        sUr[k*WP + o] = Ur[(size_t)(ot*32 + o)*256 + k];
        sU [k*WP + o] = U [(size_t)(ot*32 + o)*256 + k];
    }
    const float4 ubv = *(const float4*)&Ub[o_0];
    __syncthreads();

    const int b0 = ct*64 + c0;
    const float* myaT = g_aT + b0;

    for (int t = 0; t < 64; t++) {
        const float* Cin  = (t & 1) ? Cb : Ca;
        float*       Cout = (t & 1) ? Ca : Cb;

        // Stage C tile k-major (skip own out-slice after t=0; warp-uniform pred)
        #pragma unroll
        for (int e8 = 0; e8 < 4; e8++) {
            float tmp[8];
            #pragma unroll
            for (int u = 0; u < 8; u++) {
                int idx = (e8*8 + u)*512 + tid;
                int k = idx & 255;
                if (t == 0 || (k >> 5) != ot)
                    tmp[u] = Cin[(size_t)(ct*64 + (idx >> 8))*256 + k];
            }
            #pragma unroll
            for (int u = 0; u < 8; u++) {
                int idx = (e8*8 + u)*512 + tid;
                int k = idx & 255;
                if (t == 0 || (k >> 5) != ot)
                    sC[k*CP + (idx >> 8)] = tmp[u];
            }
        }
        __syncthreads();

        uint64_t aU0a=0ull, aU1a=0ull, aV0a=0ull, aV1a=0ull;   // chain 0
        uint64_t aU0b=0ull, aU1b=0ull, aV0b=0ull, aV1b=0ull;   // chain 1

        const float* wr = sUr + (size_t)kbase*WP + o0;
        const float* wu = sU  + (size_t)kbase*WP + o0;
        const float* cB = sC  + (size_t)kbase*CP + c0;
        #pragma unroll 4
        for (int kk = 0; kk < 128; kk++) {
            float2 cv = *(const float2*)&cB[kk*CP];       // LDS.64
            uint64_t cp0 = packf2(cv.x);
            uint64_t cp1 = packf2(cv.y);
            const float4 urv = *(const float4*)&wr[kk*WP]; // LDS.128 broadcast
            const float4 uv  = *(const float4*)&wu[kk*WP];
            const uint64_t ur01 = *(const uint64_t*)&urv.x;
            const uint64_t ur23 = *(const uint64_t*)&urv.z;
            const uint64_t u01  = *(const uint64_t*)&uv.x;
            const uint64_t u23  = *(const uint64_t*)&uv.z;
            fma2(aU0a, cp0, ur01); fma2(aU1a, cp0, ur23);
            fma2(aV0a, cp0, u01);  fma2(aV1a, cp0, u23);
            fma2(aU0b, cp1, ur01); fma2(aU1b, cp1, ur23);
            fma2(aV0b, cp1, u01);  fma2(aV1b, cp1, u23);
        }

        // Merge upper-half partials into lower half
        if (khalf) {
            red64[0*256 + rid] = aU0a; red64[1*256 + rid] = aU1a;
            red64[2*256 + rid] = aV0a; red64[3*256 + rid] = aV1a;
            red64[4*256 + rid] = aU0b; red64[5*256 + rid] = aU1b;
            red64[6*256 + rid] = aV0b; red64[7*256 + rid] = aV1b;
        }
        __syncthreads();

        if (!khalf) {
            add2(aU0a, red64[0*256 + rid]); add2(aU1a, red64[1*256 + rid]);
            add2(aV0a, red64[2*256 + rid]); add2(aV1a, red64[3*256 + rid]);
            add2(aU0b, red64[4*256 + rid]); add2(aU1b, red64[5*256 + rid]);
            add2(aV0b, red64[6*256 + rid]); add2(aV1b, red64[7*256 + rid]);

            // Epilogue
            const size_t trow = (size_t)(ct*64 + t) * 256;
            const float4 a1v = *(const float4*)&g_A1[trow + o_0];
            const float4 a2v = *(const float4*)&g_A2[trow + o_0];
            const float2 gg  = *(const float2*)&myaT[t*1024];

            float4 resA, resB;
            {
                float2 su01 = unpackf2(aU0a);
                float2 su23 = unpackf2(aU1a);
                float2 sv01 = unpackf2(aV0a);
                float2 sv23 = unpackf2(aV1a);
                const float g = gg.x;
                const int c = c0;
                float ci0 = sC[(o_0 + 0)*CP + c];
                float ci1 = sC[(o_0 + 1)*CP + c];
                float ci2 = sC[(o_0 + 2)*CP + c];
                float ci3 = sC[(o_0 + 3)*CP + c];
                float r0 = fast_sigmoid(su01.x + a1v.x);
                resA.x = g*fast_tanh(a2v.x + r0*(sv01.x + ubv.x)) + (1.0f - g)*ci0;
                float r1 = fast_sigmoid(su01.y + a1v.y);
                resA.y = g*fast_tanh(a2v.y + r1*(sv01.y + ubv.y)) + (1.0f - g)*ci1;
                float r2 = fast_sigmoid(su23.x + a1v.z);
                resA.z = g*fast_tanh(a2v.z + r2*(sv23.x + ubv.z)) + (1.0f - g)*ci2;
                float r3 = fast_sigmoid(su23.y + a1v.w);
                resA.w = g*fast_tanh(a2v.w + r3*(sv23.y + ubv.w)) + (1.0f - g)*ci3;
            }
            {
                float2 su01 = unpackf2(aU0b);
                float2 su23 = unpackf2(aU1b);
                float2 sv01 = unpackf2(aV0b);
                float2 sv23 = unpackf2(aV1b);
                const float g = gg.y;
                const int c = c0 + 1;
                float ci0 = sC[(o_0 + 0)*CP + c];
                float ci1 = sC[(o_0 + 1)*CP + c];
                float ci2 = sC[(o_0 + 2)*CP + c];
                float ci3 = sC[(o_0 + 3)*CP + c];
                float r0 = fast_sigmoid(su01.x + a1v.x);
                resB.x = g*fast_tanh(a2v.x + r0*(sv01.x + ubv.x)) + (1.0f - g)*ci0;
                float r1 = fast_sigmoid(su01.y + a1v.y);
                resB.y = g*fast_tanh(a2v.y + r1*(sv01.y + ubv.y)) + (1.0f - g)*ci1;
                float r2 = fast_sigmoid(su23.x + a1v.z);
                resB.z = g*fast_tanh(a2v.z + r2*(sv23.x + ubv.z)) + (1.0f - g)*ci2;
                float r3 = fast_sigmoid(su23.y + a1v.w);
                resB.w = g*fast_tanh(a2v.w + r3*(sv23.y + ubv.w)) + (1.0f - g)*ci3;
            }

            // Write to gmem for peer CTAs
            *(float4*)&Cout[(size_t)(ct*64 + c0    )*256 + o_0] = resA;
            *(float4*)&Cout[(size_t)(ct*64 + c0 + 1)*256 + o_0] = resB;
            // Keep own slice in smem (staging skips it next step)
            *(float2*)&sC[(o_0 + 0)*CP + c0] = make_float2(resA.x, resB.x);
            *(float2*)&sC[(o_0 + 1)*CP + c0] = make_float2(resA.y, resB.y);
            *(float2*)&sC[(o_0 + 2)*CP + c0] = make_float2(resA.z, resB.z);
            *(float2*)&sC[(o_0 + 3)*CP + c0] = make_float2(resA.w, resB.w);
        }

        // Cluster-wide step barrier (release/acquire + L1D flush)
        if (t < 63) {
            asm volatile("barrier.cluster.arrive.aligned;" ::: "memory");
            asm volatile("barrier.cluster.wait.aligned;" ::: "memory");
        }
    }
}

// ---------------------------------------------------------------------------
// next_mem = relu([prevM, C, questions] @ nm_w^T + nm_b).
// ---------------------------------------------------------------------------
__global__ void final_kernel(const float* __restrict__ prevM,
                             const float* __restrict__ questions,
                             const float* __restrict__ C,
                             const float* __restrict__ nmw,
                             const float* __restrict__ nmb,
                             float* __restrict__ out)
{
    __shared__ float sX[64*36];
    __shared__ float sW[64*68];
    const int rt = blockIdx.x;
    const int ot = blockIdx.y;
    const int tid = threadIdx.x;
    const int tr = tid & 7, to = tid >> 3;
    const int r0 = tr*4, o0 = to*2;

    float acc[4][2];
    #pragma unroll
    for (int a = 0; a < 4; a++) { acc[a][0]=acc[a][1]=0.0f; }

    for (int k0 = 0; k0 < 768; k0 += 64) {
        __syncthreads();
        #pragma unroll
        for (int e = 0; e < 8; e++) {
            int idx = e*256 + tid;
            int r = idx >> 6, k = idx & 63;
            int kg = k0 + k;
            const float* src; int off;
            if (kg < 256)      { src = prevM;     off = kg; }
            else if (kg < 512) { src = C;         off = kg - 256; }
            else               { src = questions; off = kg - 512; }
            sX[k*36 + r] = src[(size_t)(rt*32 + r)*256 + off];
        }
        #pragma unroll
        for (int e = 0; e < 16; e++) {
            int idx = e*256 + tid;
            int o = idx >> 6, k = idx & 63;
            sW[k*68 + o] = nmw[(size_t)(ot*64 + o)*768 + k0 + k];
        }
        __syncthreads();
        #pragma unroll 4
        for (int k = 0; k < 64; k++) {
            float4 xv = *(const float4*)&sX[k*36 + r0];
            float2 wv = *(const float2*)&sW[k*68 + o0];
            acc[0][0]+=xv.x*wv.x; acc[0][1]+=xv.x*wv.y;
            acc[1][0]+=xv.y*wv.x; acc[1][1]+=xv.y*wv.y;
            acc[2][0]+=xv.z*wv.x; acc[2][1]+=xv.z*wv.y;
            acc[3][0]+=xv.w*wv.x; acc[3][1]+=xv.w*wv.y;
        }
    }
    #pragma unroll
    for (int rr = 0; rr < 4; rr++)
        #pragma unroll
        for (int oo = 0; oo < 2; oo++) {
            int o = ot*64 + o0 + oo;
            float v = acc[rr][oo] + nmb[o];
            out[(size_t)(rt*32 + r0 + rr)*256 + o] = fmaxf(v, 0.0f);
        }
}

// ---------------------------------------------------------------------------
extern "C" void kernel_launch(void* const* d_in, const int* in_sizes, int n_in,
                              void* d_out, int out_size)
{
    const float* facts     = (const float*)d_in[0];
    const float* prevM     = (const float*)d_in[1];
    const float* questions = (const float*)d_in[2];
    const int*   doc_len   = (const int*)  d_in[3];
    const float* z1w = (const float*)d_in[4];
    const float* z1b = (const float*)d_in[5];
    const float* z2w = (const float*)d_in[6];
    const float* z2b = (const float*)d_in[7];
    const float* Wrw = (const float*)d_in[8];
    const float* Wrb = (const float*)d_in[9];
    const float* Urw = (const float*)d_in[10];
    const float* Urb = (const float*)d_in[11];
    const float* Ww  = (const float*)d_in[12];
    const float* Wb  = (const float*)d_in[13];
    const float* Uw  = (const float*)d_in[14];
    const float* Ub  = (const float*)d_in[15];
    const float* nmw = (const float*)d_in[16];
    const float* nmb = (const float*)d_in[17];

    float* out      = (float*)d_out;              // next_mem first
    float* out_attn = out + NM_ELEMS;             // attn second

    cudaFuncSetAttribute(gate_kernel,
                         cudaFuncAttributeMaxDynamicSharedMemorySize, GATE_SMEM_BYTES);
    cudaFuncSetAttribute(gru_persistent,
                         cudaFuncAttributeMaxDynamicSharedMemorySize, GRU_SMEM_BYTES);

    float *Ca, *Cb;
    cudaGetSymbolAddress((void**)&Ca, g_Ca);
    cudaGetSymbolAddress((void**)&Cb, g_Cb);

    // gru at launch index 3 -> ncu captures the GRU.
    splitw_kernel<<<256, 256>>>(z1w);                                   // 0
    a12_kernel<<<dim3(16, 8), 256>>>(facts, Wrw, Wrb, Urb, Ww, Wb);     // 1
    gate_kernel<<<512, 512, GATE_SMEM_BYTES>>>(facts, prevM, questions, // 2
                                               z1b, z2w, z2b, doc_len, out_attn);
    gru_persistent<<<STEP_CTAS, 512, GRU_SMEM_BYTES>>>(Ca, Cb, Urw, Uw, Ub); // 3
    // After t=63 (odd), final C lives in Ca
    final_kernel<<<dim3(32, 4), 256>>>(prevM, questions, Ca, nmw, nmb, out); // 4
}

// round 16
// speedup vs baseline: 1.3533x; 1.3533x over previous
#include <cuda_runtime.h>
#include <cuda_bf16.h>
#include <math.h>
#include <math_constants.h>
#include <stdint.h>

// Problem dims
#define Nn 16
#define Ss 64
#define Hh 256
#define FAa 256
#define Bb (Nn*Ss)              // 1024 chains / rows
#define NM_ELEMS (Nn*Ss*Hh)     // 262144
#define ATTN_ELEMS (Nn*Ss*Ss)   // 65536
#define STEP_CTAS 128

// Scratch (device globals: no allocation allowed)
__device__ float g_A1[Bb*Hh];
__device__ float g_A2[Bb*Hh];
__device__ float g_Ca[Bb*Hh];
__device__ float g_Cb[Bb*Hh];
__device__ float g_aT[Ss*Bb];               // attn transposed: [t][b]
__device__ __nv_bfloat16 g_Whi[256*1024];   // z1w split hi
__device__ __nv_bfloat16 g_Wlo[256*1024];   // z1w split lo

// Group barrier state: one flag per CTA; CTA (ct,ot) syncs with (ct,0..7)
__device__ unsigned g_flags[STEP_CTAS];

// ---------------------------------------------------------------------------
// Helpers
// ---------------------------------------------------------------------------
__device__ __forceinline__ float fast_tanh(float x)
{
    float e = __expf(2.0f * x);
    return 1.0f - __fdividef(2.0f, e + 1.0f);
}
__device__ __forceinline__ float fast_sigmoid(float x)
{
    float e = __expf(-x);
    return __fdividef(1.0f, 1.0f + e);
}

// ---- packed fp32x2 (B300 FFMA2) ----
__device__ __forceinline__ uint64_t packf2(float x)
{
    uint64_t r;
    uint32_t u = __float_as_uint(x);
    asm("mov.b64 %0, {%1, %1};" : "=l"(r) : "r"(u));
    return r;
}
__device__ __forceinline__ void fma2(uint64_t& d, uint64_t a, uint64_t b)
{
    asm("fma.rn.f32x2 %0, %1, %2, %0;" : "+l"(d) : "l"(a), "l"(b));
}
__device__ __forceinline__ void add2(uint64_t& d, uint64_t a)
{
    asm("add.rn.f32x2 %0, %0, %1;" : "+l"(d) : "l"(a));
}
__device__ __forceinline__ float2 unpackf2(uint64_t v)
{
    float2 f;
    asm("mov.b64 {%0, %1}, %2;" : "=f"(f.x), "=f"(f.y) : "l"(v));
    return f;
}

// Pack two floats to bf16x2 and residual pack.
__device__ __forceinline__ uint32_t split2(float x, float y, uint32_t& lo)
{
    uint32_t hi;
    asm("cvt.rn.bf16x2.f32 %0, %1, %2;" : "=r"(hi) : "f"(y), "f"(x));
    float xr = x - __uint_as_float(hi << 16);
    float yr = y - __uint_as_float(hi & 0xffff0000u);
    asm("cvt.rn.bf16x2.f32 %0, %1, %2;" : "=r"(lo) : "f"(yr), "f"(xr));
    return hi;
}

__device__ __forceinline__ void mma_bf16(float* d, const uint32_t* a,
                                         uint32_t b0, uint32_t b1)
{
    asm volatile(
        "mma.sync.aligned.m16n8k16.row.col.f32.bf16.bf16.f32 "
        "{%0,%1,%2,%3}, {%4,%5,%6,%7}, {%8,%9}, {%0,%1,%2,%3};"
        : "+f"(d[0]), "+f"(d[1]), "+f"(d[2]), "+f"(d[3])
        : "r"(a[0]), "r"(a[1]), "r"(a[2]), "r"(a[3]), "r"(b0), "r"(b1));
}

__device__ __forceinline__ void ldm_x4(uint32_t* r, uint32_t addr)
{
    asm volatile("ldmatrix.sync.aligned.m8n8.x4.shared.b16 {%0,%1,%2,%3}, [%4];"
        : "=r"(r[0]), "=r"(r[1]), "=r"(r[2]), "=r"(r[3]) : "r"(addr));
}

__device__ __forceinline__ void cp16(uint32_t dst, const void* src)
{
    asm volatile("cp.async.cg.shared.global [%0], [%1], 16;" :: "r"(dst), "l"(src));
}

// ---------------------------------------------------------------------------
// Pre-split z1w into bf16 hi/lo
// ---------------------------------------------------------------------------
__global__ void splitw_kernel(const float* __restrict__ z1w) {
    int i = blockIdx.x * 256 + threadIdx.x;
    #pragma unroll
    for (int e = 0; e < 4; e++) {
        int idx = e * 65536 + i;
        float w = z1w[idx];
        __nv_bfloat16 h = __float2bfloat16_rn(w);
        g_Whi[idx] = h;
        g_Wlo[idx] = __float2bfloat16_rn(w - __bfloat162float(h));
    }
}

// ---------------------------------------------------------------------------
// A1/A2 precompute + fused zero of Ca and barrier flags.
// ---------------------------------------------------------------------------
__global__ void a12_kernel(const float* __restrict__ facts,
                           const float* __restrict__ Wr, const float* __restrict__ Wrb,
                           const float* __restrict__ Urb,
                           const float* __restrict__ W,  const float* __restrict__ Wb)
{
    __shared__ float sX[64*68];
    __shared__ float sWm[64*68];
    const int rt = blockIdx.x;
    const int yy = blockIdx.y;
    const bool first = (yy < 4);
    const int ot = first ? yy : yy - 4;
    const float* Wm = first ? Wr : W;
    float* outp = first ? g_A1 : g_A2;

    const int tid = threadIdx.x;
    const int bid = blockIdx.y * 16 + blockIdx.x;   // 0..127

    #pragma unroll
    for (int e = 0; e < 8; e++)
        g_Ca[bid*2048 + e*256 + tid] = 0.0f;
    if (bid == 0 && tid < STEP_CTAS) g_flags[tid] = 0u;

    const int tr = tid & 15, to = tid >> 4;
    const int r0 = tr*4, o0 = to*4;
    uint64_t accp[4][2];
    #pragma unroll
    for (int a = 0; a < 4; a++) { accp[a][0] = 0ull; accp[a][1] = 0ull; }

    for (int k0 = 0; k0 < 256; k0 += 64) {
        __syncthreads();
        #pragma unroll
        for (int e = 0; e < 16; e++) {
            int idx = e*256 + tid;
            int r = idx >> 6, k = idx & 63;
            sX[k*68 + r]  = facts[(size_t)(rt*64 + r)*256 + k0 + k];
            int o = r;
            sWm[k*68 + o] = Wm[(size_t)(ot*64 + o)*256 + k0 + k];
        }
        __syncthreads();
        #pragma unroll 4
        for (int k = 0; k < 64; k++) {
            float4 xv = *(const float4*)&sX[k*68 + r0];
            uint64_t w01 = *(const uint64_t*)&sWm[k*68 + o0];
            uint64_t w23 = *(const uint64_t*)&sWm[k*68 + o0 + 2];
            uint64_t p0 = packf2(xv.x), p1 = packf2(xv.y);
            uint64_t p2 = packf2(xv.z), p3 = packf2(xv.w);
            fma2(accp[0][0], p0, w01); fma2(accp[0][1], p0, w23);
            fma2(accp[1][0], p1, w01); fma2(accp[1][1], p1, w23);
            fma2(accp[2][0], p2, w01); fma2(accp[2][1], p2, w23);
            fma2(accp[3][0], p3, w01); fma2(accp[3][1], p3, w23);
        }
    }
    #pragma unroll
    for (int rr = 0; rr < 4; rr++) {
        float2 lo = unpackf2(accp[rr][0]);
        float2 hi = unpackf2(accp[rr][1]);
        float vals[4] = {lo.x, lo.y, hi.x, hi.y};
        #pragma unroll
        for (int oo = 0; oo < 4; oo++) {
            int o = ot*64 + o0 + oo;
            float bias = first ? (Wrb[o] + Urb[o]) : Wb[o];
            outp[(size_t)(rt*64 + r0 + rr)*256 + o] = vals[oo] + bias;
        }
    }
}

// ---------------------------------------------------------------------------
// Gate MLP via bf16-split mma.sync + fused masked softmax (attn + attnT).
// ---------------------------------------------------------------------------
#define SFP     268
#define WOFF    0
#define WBUFSZ  73728
#define WHALF   36864
#define SFOFF   147456
#define QOFF    (SFOFF + 68608)
#define B1OFF   (QOFF + 4096)
#define Z2OFF   (B1OFF + 1024)
#define REDOFF  (Z2OFF + 1024)
#define SGOFF   (REDOFF + 8192)
#define GATE_SMEM_BYTES (SGOFF + 512)

__global__ void __launch_bounds__(512, 1)
gate_kernel(const float* __restrict__ facts,
            const float* __restrict__ prevM,
            const float* __restrict__ questions,
            const float* __restrict__ z1b,
            const float* __restrict__ z2w,
            const float* __restrict__ z2b,
            const int* __restrict__ doc_len,
            float* __restrict__ out_attn)
{
    extern __shared__ char smc[];
    float* sf  = (float*)(smc + SFOFF);
    float* sQ0 = (float*)(smc + QOFF);
    float* sQ1 = sQ0 + 256;
    float* sM0 = sQ1 + 256;
    float* sM1 = sM0 + 256;
    float* sb1 = (float*)(smc + B1OFF);
    float* sz2 = (float*)(smc + Z2OFF);
    float* red = (float*)(smc + REDOFF);
    float* sG  = (float*)(smc + SGOFF);
    const uint32_t smbase = (uint32_t)__cvta_generic_to_shared(smc);

    const int tid  = threadIdx.x;
    const int lane = tid & 31;
    const int wid  = tid >> 5;
    const int g    = lane >> 2;
    const int tg   = lane & 3;
    const int wm   = wid & 3;
    const int wn   = wid >> 2;

    const int bx  = blockIdx.x;
    const int n   = bx >> 5;
    const int ip  = bx & 31;
    const int ni0 = n*64 + ip*2;

    {
        const float2* f2 = (const float2*)(facts + (size_t)n * Ss * Hh);
        #pragma unroll
        for (int e = 0; e < 16; e++) {
            int idx = e*512 + tid;
            int j = idx >> 7, h2 = idx & 127;
            *(float2*)&sf[j*SFP + h2*2] = f2[idx];
        }
        if (tid < 256) {
            sQ0[tid] = questions[(size_t)ni0*256 + tid];
            sQ1[tid] = questions[(size_t)(ni0+1)*256 + tid];
            sM0[tid] = prevM[(size_t)ni0*256 + tid];
            sM1[tid] = prevM[(size_t)(ni0+1)*256 + tid];
            sb1[tid] = z1b[tid];
            sz2[tid] = z2w[tid];
        }
    }

    const int wrow  = tid >> 1;
    const int whalf = tid & 1;

    {
        const char* gh = (const char*)(g_Whi + (size_t)wrow*1024 + whalf*32);
        const char* gl = (const char*)(g_Wlo + (size_t)wrow*1024 + whalf*32);
        uint32_t dh = smbase + WOFF + (uint32_t)(wrow*144 + whalf*64);
        uint32_t dl = dh + WHALF;
        #pragma unroll
        for (int u = 0; u < 4; u++) { cp16(dh + u*16, gh + u*16); cp16(dl + u*16, gl + u*16); }
        asm volatile("cp.async.commit_group;");
        asm volatile("cp.async.wait_group 0;");
    }
    __syncthreads();

    float acc[2][8][4];
    #pragma unroll
    for (int mt = 0; mt < 2; mt++)
        #pragma unroll
        for (int nt = 0; nt < 8; nt++)
            #pragma unroll
            for (int v = 0; v < 4; v++) acc[mt][nt][v] = 0.0f;

    const uint32_t broff = (uint32_t)((wn*64 + ((lane>>4)&1)*8 + (lane&7)) * 144
                                      + ((lane>>3)&1)*16);

    for (int c = 0; c < 16; c++) {
        if (c < 15) {
            const char* gh = (const char*)(g_Whi + (size_t)wrow*1024 + (c+1)*64 + whalf*32);
            const char* gl = (const char*)(g_Wlo + (size_t)wrow*1024 + (c+1)*64 + whalf*32);
            uint32_t dh = smbase + WOFF + (uint32_t)(((c+1)&1)*WBUFSZ)
                        + (uint32_t)(wrow*144 + whalf*64);
            uint32_t dl = dh + WHALF;
            #pragma unroll
            for (int u = 0; u < 4; u++) { cp16(dh + u*16, gh + u*16); cp16(dl + u*16, gl + u*16); }
            asm volatile("cp.async.commit_group;");
        }

        const int  bterm = c >> 2;
        const int  h0    = (c & 3) * 64;
        const bool isabs = (bterm >= 2);
        const uint32_t wbase = smbase + WOFF + (uint32_t)((c&1)*WBUFSZ);

        #pragma unroll
        for (int ks = 0; ks < 4; ks++) {
            const int h = h0 + ks*16;

            uint32_t Ah[2][4], Al[2][4];
            #pragma unroll
            for (int mt = 0; mt < 2; mt++) {
                const int rb   = wm*32 + mt*16 + g;
                const int isel = rb >> 6;
                const float* tv = (bterm & 1) ? (isel ? sM1 : sM0)
                                              : (isel ? sQ1 : sQ0);
                const int j0 = rb & 63;
                const float* fr0 = &sf[j0*SFP + h + tg*2];
                const float* fr1 = fr0 + 8*SFP;
                float2 t0  = *(const float2*)&tv[h + tg*2];
                float2 t1  = *(const float2*)&tv[h + tg*2 + 8];
                float2 fa  = *(const float2*)fr0;
                float2 fA  = *(const float2*)(fr0 + 8);
                float2 fb  = *(const float2*)fr1;
                float2 fB  = *(const float2*)(fr1 + 8);
                float z00, z01, z10, z11, z20, z21, z30, z31;
                if (isabs) {
                    z00 = fabsf(fa.x - t0.x); z01 = fabsf(fa.y - t0.y);
                    z10 = fabsf(fb.x - t0.x); z11 = fabsf(fb.y - t0.y);
                    z20 = fabsf(fA.x - t1.x); z21 = fabsf(fA.y - t1.y);
                    z30 = fabsf(fB.x - t1.x); z31 = fabsf(fB.y - t1.y);
                } else {
                    z00 = fa.x * t0.x; z01 = fa.y * t0.y;
                    z10 = fb.x * t0.x; z11 = fb.y * t0.y;
                    z20 = fA.x * t1.x; z21 = fA.y * t1.y;
                    z30 = fB.x * t1.x; z31 = fB.y * t1.y;
                }
                Ah[mt][0] = split2(z00, z01, Al[mt][0]);
                Ah[mt][1] = split2(z10, z11, Al[mt][1]);
                Ah[mt][2] = split2(z20, z21, Al[mt][2]);
                Ah[mt][3] = split2(z30, z31, Al[mt][3]);
            }

            #pragma unroll
            for (int pass = 0; pass < 3; pass++) {
                const uint32_t* A0 = (pass == 1) ? Al[0] : Ah[0];
                const uint32_t* A1 = (pass == 1) ? Al[1] : Ah[1];
                const uint32_t hoff = (pass == 2) ? (uint32_t)WHALF : 0u;
                #pragma unroll
                for (int p = 0; p < 4; p++) {
                    uint32_t bfr[4];
                    ldm_x4(bfr, wbase + broff + (uint32_t)(p*16*144 + ks*32) + hoff);
                    mma_bf16(acc[0][p*2],   A0, bfr[0], bfr[1]);
                    mma_bf16(acc[1][p*2],   A1, bfr[0], bfr[1]);
                    mma_bf16(acc[0][p*2+1], A0, bfr[2], bfr[3]);
                    mma_bf16(acc[1][p*2+1], A1, bfr[2], bfr[3]);
                }
            }
        }

        if (c < 15) asm volatile("cp.async.wait_group 0;");
        __syncthreads();
    }

    #pragma unroll
    for (int mt = 0; mt < 2; mt++) {
        #pragma unroll
        for (int rh = 0; rh < 2; rh++) {
            const int r = wm*32 + mt*16 + rh*8 + g;
            float s = 0.0f;
            #pragma unroll
            for (int nt = 0; nt < 8; nt++) {
                #pragma unroll
                for (int cc = 0; cc < 2; cc++) {
                    const int a = wn*64 + nt*8 + tg*2 + cc;
                    float x = acc[mt][nt][rh*2 + cc] + sb1[a];
                    s += fast_tanh(x) * sz2[a];
                }
            }
            red[r*16 + wn*4 + tg] = s;
        }
    }
    __syncthreads();
    if (tid < 128) {
        float G = z2b[0];
        #pragma unroll
        for (int u = 0; u < 16; u++) G += red[tid*16 + u];
        sG[tid] = G;
    }
    __syncthreads();
    if (wid < 2) {
        const int row = wid;
        const int dl  = doc_len[n];
        const int b   = ni0 + row;
        float v0 = sG[row*64 + lane];
        float v1 = sG[row*64 + 32 + lane];
        float x0 = (lane      < dl && v0 != 0.0f) ? v0 : -CUDART_INF_F;
        float x1 = (lane + 32 < dl && v1 != 0.0f) ? v1 : -CUDART_INF_F;
        float mx = fmaxf(x0, x1);
        #pragma unroll
        for (int o = 16; o >= 1; o >>= 1)
            mx = fmaxf(mx, __shfl_xor_sync(0xffffffffu, mx, o));
        float e0 = expf(x0 - mx);
        float e1 = expf(x1 - mx);
        float s = e0 + e1;
        #pragma unroll
        for (int o = 16; o >= 1; o >>= 1)
            s += __shfl_xor_sync(0xffffffffu, s, o);
        float inv = 1.0f / s;
        float a0 = e0 * inv, a1 = e1 * inv;
        out_attn[b*64 + lane]      = a0;
        out_attn[b*64 + 32 + lane] = a1;
        g_aT[lane*1024 + b]        = a0;
        g_aT[(lane+32)*1024 + b]   = a1;
    }
}

// ---------------------------------------------------------------------------
// Persistent GRU, split-K: 128 CTAs x 512 threads (16 warps = 4/SMSP).
// Inter-step sync = per-chain-tile GROUP barrier: CTA (ct,ot) only waits for
// CTAs (ct,0..7) — single-phase flag array, no central aggregation.
// ---------------------------------------------------------------------------
#define WP 40
#define CP 66
#define GRED_U64 (8*256)
#define GRU_SMEM_BYTES ((2*256*WP + 256*CP)*4 + GRED_U64*8)  // 165888

__device__ __forceinline__ void group_barrier(unsigned expect, int ct)
{
    const int tid = threadIdx.x;
    __syncthreads();
    if (tid == 0) {
        __threadfence();
        asm volatile("st.release.gpu.u32 [%0], %1;"
                     :: "l"(&g_flags[blockIdx.x]), "r"(expect) : "memory");
    }
    if (tid < 8) {
        unsigned v;
        do {
            asm volatile("ld.acquire.gpu.u32 %0, [%1];"
                         : "=r"(v) : "l"(&g_flags[ct*8 + tid]) : "memory");
        } while (v < expect);
    }
    __syncthreads();
}

__global__ void __launch_bounds__(512, 1)
gru_persistent(float* __restrict__ Ca, float* __restrict__ Cb,
               const float* __restrict__ Ur, const float* __restrict__ U,
               const float* __restrict__ Ub)
{
    extern __shared__ float smem[];
    float* sUr = smem;                      // 256 x 40 (k x o)
    float* sU  = sUr + 256*WP;
    float* sC  = sU  + 256*WP;              // 256 x 66 (k x chain)
    uint64_t* red64 = (uint64_t*)(sC + 256*CP);   // 8 x 256

    const int bx  = blockIdx.x;
    const int ct  = bx >> 3;                // chain tile (16), 64 chains
    const int ot  = bx & 7;                 // out tile (8), 32 outs
    const int tid = threadIdx.x;
    const int rid = tid & 255;
    const int khalf = tid >> 8;             // 0: k<128, 1: k>=128
    const int c0  = (rid & 31) * 2;         // 2 chains
    const int o0  = (rid >> 5) * 4;         // 4 outs
    const int o_0 = ot*32 + o0;
    const int kbase = khalf * 128;

    // Load weight slices once (512 threads)
    #pragma unroll
    for (int e = 0; e < 16; e++) {
        int idx = e*512 + tid;
        int o = idx >> 8, k = idx & 255;
        sUr[k*WP + o] = Ur[(size_t)(ot*32 + o)*256 + k];
        sU [k*WP + o] = U [(size_t)(ot*32 + o)*256 + k];
    }
    const float4 ubv = *(const float4*)&Ub[o_0];
    __syncthreads();

    const int b0 = ct*64 + c0;
    const float* myaT = g_aT + b0;

    for (int t = 0; t < 64; t++) {
        const float* Cin  = (t & 1) ? Cb : Ca;
        float*       Cout = (t & 1) ? Ca : Cb;

        // Stage FULL C tile (16384 elems), k-major; 4 batches of 8
        #pragma unroll
        for (int e8 = 0; e8 < 4; e8++) {
            float tmp[8];
            #pragma unroll
            for (int u = 0; u < 8; u++) {
                int idx = (e8*8 + u)*512 + tid;
                tmp[u] = Cin[(size_t)(ct*64 + (idx >> 8))*256 + (idx & 255)];
            }
            #pragma unroll
            for (int u = 0; u < 8; u++) {
                int idx = (e8*8 + u)*512 + tid;
                sC[(idx & 255)*CP + (idx >> 8)] = tmp[u];
            }
        }
        __syncthreads();

        uint64_t aU0a=0ull, aU1a=0ull, aV0a=0ull, aV1a=0ull;   // chain 0
        uint64_t aU0b=0ull, aU1b=0ull, aV0b=0ull, aV1b=0ull;   // chain 1

        const float* wr = sUr + (size_t)kbase*WP + o0;
        const float* wu = sU  + (size_t)kbase*WP + o0;
        const float* cB = sC  + (size_t)kbase*CP + c0;
        #pragma unroll 4
        for (int kk = 0; kk < 128; kk++) {
            float2 cv = *(const float2*)&cB[kk*CP];       // LDS.64
            uint64_t cp0 = packf2(cv.x);
            uint64_t cp1 = packf2(cv.y);
            const float4 urv = *(const float4*)&wr[kk*WP]; // LDS.128 broadcast
            const float4 uv  = *(const float4*)&wu[kk*WP];
            const uint64_t ur01 = *(const uint64_t*)&urv.x;
            const uint64_t ur23 = *(const uint64_t*)&urv.z;
            const uint64_t u01  = *(const uint64_t*)&uv.x;
            const uint64_t u23  = *(const uint64_t*)&uv.z;
            fma2(aU0a, cp0, ur01); fma2(aU1a, cp0, ur23);
            fma2(aV0a, cp0, u01);  fma2(aV1a, cp0, u23);
            fma2(aU0b, cp1, ur01); fma2(aU1b, cp1, ur23);
            fma2(aV0b, cp1, u01);  fma2(aV1b, cp1, u23);
        }

        // Merge upper-half partials into lower half (packed adds)
        if (khalf) {
            red64[0*256 + rid] = aU0a; red64[1*256 + rid] = aU1a;
            red64[2*256 + rid] = aV0a; red64[3*256 + rid] = aV1a;
            red64[4*256 + rid] = aU0b; red64[5*256 + rid] = aU1b;
            red64[6*256 + rid] = aV0b; red64[7*256 + rid] = aV1b;
        }
        __syncthreads();

        if (!khalf) {
            add2(aU0a, red64[0*256 + rid]); add2(aU1a, red64[1*256 + rid]);
            add2(aV0a, red64[2*256 + rid]); add2(aV1a, red64[3*256 + rid]);
            add2(aU0b, red64[4*256 + rid]); add2(aU1b, red64[5*256 + rid]);
            add2(aV0b, red64[6*256 + rid]); add2(aV1b, red64[7*256 + rid]);

            // Epilogue
            const size_t trow = (size_t)(ct*64 + t) * 256;
            const float4 a1v = *(const float4*)&g_A1[trow + o_0];
            const float4 a2v = *(const float4*)&g_A2[trow + o_0];
            const float2 gg  = *(const float2*)&myaT[t*1024];

            #pragma unroll
            for (int cc = 0; cc < 2; cc++) {
                const int c = c0 + cc;
                const float g = (cc == 0) ? gg.x : gg.y;
                float2 su01 = unpackf2(cc ? aU0b : aU0a);
                float2 su23 = unpackf2(cc ? aU1b : aU1a);
                float2 sv01 = unpackf2(cc ? aV0b : aV0a);
                float2 sv23 = unpackf2(cc ? aV1b : aV1a);
                float ci0 = sC[(o_0 + 0)*CP + c];
                float ci1 = sC[(o_0 + 1)*CP + c];
                float ci2 = sC[(o_0 + 2)*CP + c];
                float ci3 = sC[(o_0 + 3)*CP + c];

                float4 res;
                {
                    float r = fast_sigmoid(su01.x + a1v.x);
                    float h = fast_tanh(a2v.x + r * (sv01.x + ubv.x));
                    res.x = g*h + (1.0f - g)*ci0;
                }
                {
                    float r = fast_sigmoid(su01.y + a1v.y);
                    float h = fast_tanh(a2v.y + r * (sv01.y + ubv.y));
                    res.y = g*h + (1.0f - g)*ci1;
                }
                {
                    float r = fast_sigmoid(su23.x + a1v.z);
                    float h = fast_tanh(a2v.z + r * (sv23.x + ubv.z));
                    res.z = g*h + (1.0f - g)*ci2;
                }
                {
                    float r = fast_sigmoid(su23.y + a1v.w);
                    float h = fast_tanh(a2v.w + r * (sv23.y + ubv.w));
                    res.w = g*h + (1.0f - g)*ci3;
                }
                *(float4*)&Cout[(size_t)(ct*64 + c)*256 + o_0] = res;
            }
        }

        if (t < 63) group_barrier((unsigned)(t + 1), ct);
    }
}

// ---------------------------------------------------------------------------
// next_mem = relu([prevM, C, questions] @ nm_w^T + nm_b).
// ---------------------------------------------------------------------------
__global__ void final_kernel(const float* __restrict__ prevM,
                             const float* __restrict__ questions,
                             const float* __restrict__ C,
                             const float* __restrict__ nmw,
                             const float* __restrict__ nmb,
                             float* __restrict__ out)
{
    __shared__ float sX[64*36];
    __shared__ float sW[64*68];
    const int rt = blockIdx.x;
    const int ot = blockIdx.y;
    const int tid = threadIdx.x;
    const int tr = tid & 7, to = tid >> 3;
    const int r0 = tr*4, o0 = to*2;

    float acc[4][2];
    #pragma unroll
    for (int a = 0; a < 4; a++) { acc[a][0]=acc[a][1]=0.0f; }

    for (int k0 = 0; k0 < 768; k0 += 64) {
        __syncthreads();
        #pragma unroll
        for (int e = 0; e < 8; e++) {
            int idx = e*256 + tid;
            int r = idx >> 6, k = idx & 63;
            int kg = k0 + k;
            const float* src; int off;
            if (kg < 256)      { src = prevM;     off = kg; }
            else if (kg < 512) { src = C;         off = kg - 256; }
            else               { src = questions; off = kg - 512; }
            sX[k*36 + r] = src[(size_t)(rt*32 + r)*256 + off];
        }
        #pragma unroll
        for (int e = 0; e < 16; e++) {
            int idx = e*256 + tid;
            int o = idx >> 6, k = idx & 63;
            sW[k*68 + o] = nmw[(size_t)(ot*64 + o)*768 + k0 + k];
        }
        __syncthreads();
        #pragma unroll 4
        for (int k = 0; k < 64; k++) {
            float4 xv = *(const float4*)&sX[k*36 + r0];
            float2 wv = *(const float2*)&sW[k*68 + o0];
            acc[0][0]+=xv.x*wv.x; acc[0][1]+=xv.x*wv.y;
            acc[1][0]+=xv.y*wv.x; acc[1][1]+=xv.y*wv.y;
            acc[2][0]+=xv.z*wv.x; acc[2][1]+=xv.z*wv.y;
            acc[3][0]+=xv.w*wv.x; acc[3][1]+=xv.w*wv.y;
        }
    }
    #pragma unroll
    for (int rr = 0; rr < 4; rr++)
        #pragma unroll
        for (int oo = 0; oo < 2; oo++) {
            int o = ot*64 + o0 + oo;
            float v = acc[rr][oo] + nmb[o];
            out[(size_t)(rt*32 + r0 + rr)*256 + o] = fmaxf(v, 0.0f);
        }
}

// ---------------------------------------------------------------------------
extern "C" void kernel_launch(void* const* d_in, const int* in_sizes, int n_in,
                              void* d_out, int out_size)
{
    const float* facts     = (const float*)d_in[0];
    const float* prevM     = (const float*)d_in[1];
    const float* questions = (const float*)d_in[2];
    const int*   doc_len   = (const int*)  d_in[3];
    const float* z1w = (const float*)d_in[4];
    const float* z1b = (const float*)d_in[5];
    const float* z2w = (const float*)d_in[6];
    const float* z2b = (const float*)d_in[7];
    const float* Wrw = (const float*)d_in[8];
    const float* Wrb = (const float*)d_in[9];
    const float* Urw = (const float*)d_in[10];
    const float* Urb = (const float*)d_in[11];
    const float* Ww  = (const float*)d_in[12];
    const float* Wb  = (const float*)d_in[13];
    const float* Uw  = (const float*)d_in[14];
    const float* Ub  = (const float*)d_in[15];
    const float* nmw = (const float*)d_in[16];
    const float* nmb = (const float*)d_in[17];

    float* out      = (float*)d_out;              // next_mem first
    float* out_attn = out + NM_ELEMS;             // attn second

    cudaFuncSetAttribute(gate_kernel,
                         cudaFuncAttributeMaxDynamicSharedMemorySize, GATE_SMEM_BYTES);
    cudaFuncSetAttribute(gru_persistent,
                         cudaFuncAttributeMaxDynamicSharedMemorySize, GRU_SMEM_BYTES);

    float *Ca, *Cb;
    cudaGetSymbolAddress((void**)&Ca, g_Ca);
    cudaGetSymbolAddress((void**)&Cb, g_Cb);

    // gru at launch index 3 -> ncu captures the GRU.
    splitw_kernel<<<256, 256>>>(z1w);                                   // 0
    a12_kernel<<<dim3(16, 8), 256>>>(facts, Wrw, Wrb, Urb, Ww, Wb);     // 1
    gate_kernel<<<512, 512, GATE_SMEM_BYTES>>>(facts, prevM, questions, // 2
                                               z1b, z2w, z2b, doc_len, out_attn);
    gru_persistent<<<STEP_CTAS, 512, GRU_SMEM_BYTES>>>(Ca, Cb, Urw, Uw, Ub); // 3
    // After t=63 (odd), final C lives in Ca
    final_kernel<<<dim3(32, 4), 256>>>(prevM, questions, Ca, nmw, nmb, out); // 4
}

// round 17
// speedup vs baseline: 1.8133x; 1.3399x over previous
#include <cuda_runtime.h>
#include <cuda_bf16.h>
#include <math.h>
#include <math_constants.h>
#include <stdint.h>

// Problem dims
#define Nn 16
#define Ss 64
#define Hh 256
#define FAa 256
#define Bb (Nn*Ss)              // 1024 chains / rows
#define NM_ELEMS (Nn*Ss*Hh)     // 262144
#define ATTN_ELEMS (Nn*Ss*Ss)   // 65536
#define STEP_CTAS 128

// Scratch (device globals: no allocation allowed)
__device__ float g_A1[Bb*Hh];
__device__ float g_A2[Bb*Hh];
__device__ float g_Ca[Bb*Hh];
__device__ float g_Cb[Bb*Hh];
__device__ float g_aT[Ss*Bb];               // attn transposed: [t][b]
__device__ __nv_bfloat16 g_Whi[256*1024];   // z1w split hi
__device__ __nv_bfloat16 g_Wlo[256*1024];   // z1w split lo

// Grid barrier state (flag per CTA + generation broadcast) — R14 scheme
__device__ unsigned g_flags[STEP_CTAS];
__device__ unsigned g_gen2;

// ---------------------------------------------------------------------------
// Helpers
// ---------------------------------------------------------------------------
__device__ __forceinline__ float fast_tanh(float x)
{
    float e = __expf(2.0f * x);
    return 1.0f - __fdividef(2.0f, e + 1.0f);
}
__device__ __forceinline__ float fast_sigmoid(float x)
{
    float e = __expf(-x);
    return __fdividef(1.0f, 1.0f + e);
}

// ---- packed fp32x2 (B300 FFMA2) ----
__device__ __forceinline__ uint64_t packf2(float x)
{
    uint64_t r;
    uint32_t u = __float_as_uint(x);
    asm("mov.b64 %0, {%1, %1};" : "=l"(r) : "r"(u));
    return r;
}
__device__ __forceinline__ void fma2(uint64_t& d, uint64_t a, uint64_t b)
{
    asm("fma.rn.f32x2 %0, %1, %2, %0;" : "+l"(d) : "l"(a), "l"(b));
}
__device__ __forceinline__ float2 unpackf2(uint64_t v)
{
    float2 f;
    asm("mov.b64 {%0, %1}, %2;" : "=f"(f.x), "=f"(f.y) : "l"(v));
    return f;
}

// Pack two floats to bf16x2 (x->low, y->high) and residual pack.
__device__ __forceinline__ uint32_t split2(float x, float y, uint32_t& lo)
{
    uint32_t hi;
    asm("cvt.rn.bf16x2.f32 %0, %1, %2;" : "=r"(hi) : "f"(y), "f"(x));
    float xr = x - __uint_as_float(hi << 16);
    float yr = y - __uint_as_float(hi & 0xffff0000u);
    asm("cvt.rn.bf16x2.f32 %0, %1, %2;" : "=r"(lo) : "f"(yr), "f"(xr));
    return hi;
}

__device__ __forceinline__ void mma_bf16(float* d, const uint32_t* a,
                                         uint32_t b0, uint32_t b1)
{
    asm volatile(
        "mma.sync.aligned.m16n8k16.row.col.f32.bf16.bf16.f32 "
        "{%0,%1,%2,%3}, {%4,%5,%6,%7}, {%8,%9}, {%0,%1,%2,%3};"
        : "+f"(d[0]), "+f"(d[1]), "+f"(d[2]), "+f"(d[3])
        : "r"(a[0]), "r"(a[1]), "r"(a[2]), "r"(a[3]), "r"(b0), "r"(b1));
}

__device__ __forceinline__ void ldm_x4(uint32_t* r, uint32_t addr)
{
    asm volatile("ldmatrix.sync.aligned.m8n8.x4.shared.b16 {%0,%1,%2,%3}, [%4];"
        : "=r"(r[0]), "=r"(r[1]), "=r"(r[2]), "=r"(r[3]) : "r"(addr));
}

__device__ __forceinline__ void cp16(uint32_t dst, const void* src)
{
    asm volatile("cp.async.cg.shared.global [%0], [%1], 16;" :: "r"(dst), "l"(src));
}

// ---------------------------------------------------------------------------
// Pre-split z1w into bf16 hi/lo
// ---------------------------------------------------------------------------
__global__ void splitw_kernel(const float* __restrict__ z1w) {
    int i = blockIdx.x * 256 + threadIdx.x;
    #pragma unroll
    for (int e = 0; e < 4; e++) {
        int idx = e * 65536 + i;
        float w = z1w[idx];
        __nv_bfloat16 h = __float2bfloat16_rn(w);
        g_Whi[idx] = h;
        g_Wlo[idx] = __float2bfloat16_rn(w - __bfloat162float(h));
    }
}

// ---------------------------------------------------------------------------
// A1/A2 precompute + fused zero of Ca and barrier state.
// ---------------------------------------------------------------------------
__global__ void a12_kernel(const float* __restrict__ facts,
                           const float* __restrict__ Wr, const float* __restrict__ Wrb,
                           const float* __restrict__ Urb,
                           const float* __restrict__ W,  const float* __restrict__ Wb)
{
    __shared__ float sX[64*68];
    __shared__ float sWm[64*68];
    const int rt = blockIdx.x;
    const int yy = blockIdx.y;
    const bool first = (yy < 4);
    const int ot = first ? yy : yy - 4;
    const float* Wm = first ? Wr : W;
    float* outp = first ? g_A1 : g_A2;

    const int tid = threadIdx.x;
    const int bid = blockIdx.y * 16 + blockIdx.x;   // 0..127

    #pragma unroll
    for (int e = 0; e < 8; e++)
        g_Ca[bid*2048 + e*256 + tid] = 0.0f;
    if (bid == 0 && tid < STEP_CTAS) g_flags[tid] = 0u;
    if (bid == 0 && tid == STEP_CTAS) g_gen2 = 0u;

    const int tr = tid & 15, to = tid >> 4;
    const int r0 = tr*4, o0 = to*4;
    uint64_t accp[4][2];
    #pragma unroll
    for (int a = 0; a < 4; a++) { accp[a][0] = 0ull; accp[a][1] = 0ull; }

    for (int k0 = 0; k0 < 256; k0 += 64) {
        __syncthreads();
        #pragma unroll
        for (int e = 0; e < 16; e++) {
            int idx = e*256 + tid;
            int r = idx >> 6, k = idx & 63;
            sX[k*68 + r]  = facts[(size_t)(rt*64 + r)*256 + k0 + k];
            int o = r;
            sWm[k*68 + o] = Wm[(size_t)(ot*64 + o)*256 + k0 + k];
        }
        __syncthreads();
        #pragma unroll 4
        for (int k = 0; k < 64; k++) {
            float4 xv = *(const float4*)&sX[k*68 + r0];
            uint64_t w01 = *(const uint64_t*)&sWm[k*68 + o0];
            uint64_t w23 = *(const uint64_t*)&sWm[k*68 + o0 + 2];
            uint64_t p0 = packf2(xv.x), p1 = packf2(xv.y);
            uint64_t p2 = packf2(xv.z), p3 = packf2(xv.w);
            fma2(accp[0][0], p0, w01); fma2(accp[0][1], p0, w23);
            fma2(accp[1][0], p1, w01); fma2(accp[1][1], p1, w23);
            fma2(accp[2][0], p2, w01); fma2(accp[2][1], p2, w23);
            fma2(accp[3][0], p3, w01); fma2(accp[3][1], p3, w23);
        }
    }
    #pragma unroll
    for (int rr = 0; rr < 4; rr++) {
        float2 lo = unpackf2(accp[rr][0]);
        float2 hi = unpackf2(accp[rr][1]);
        float vals[4] = {lo.x, lo.y, hi.x, hi.y};
        #pragma unroll
        for (int oo = 0; oo < 4; oo++) {
            int o = ot*64 + o0 + oo;
            float bias = first ? (Wrb[o] + Urb[o]) : Wb[o];
            outp[(size_t)(rt*64 + r0 + rr)*256 + o] = vals[oo] + bias;
        }
    }
}

// ---------------------------------------------------------------------------
// Gate MLP via bf16-split mma.sync + fused masked softmax (attn + attnT).
// ---------------------------------------------------------------------------
#define SFP     268
#define WOFF    0
#define WBUFSZ  73728
#define WHALF   36864
#define SFOFF   147456
#define QOFF    (SFOFF + 68608)
#define B1OFF   (QOFF + 4096)
#define Z2OFF   (B1OFF + 1024)
#define REDOFF  (Z2OFF + 1024)
#define SGOFF   (REDOFF + 8192)
#define GATE_SMEM_BYTES (SGOFF + 512)

__global__ void __launch_bounds__(512, 1)
gate_kernel(const float* __restrict__ facts,
            const float* __restrict__ prevM,
            const float* __restrict__ questions,
            const float* __restrict__ z1b,
            const float* __restrict__ z2w,
            const float* __restrict__ z2b,
            const int* __restrict__ doc_len,
            float* __restrict__ out_attn)
{
    extern __shared__ char smc[];
    float* sf  = (float*)(smc + SFOFF);
    float* sQ0 = (float*)(smc + QOFF);
    float* sQ1 = sQ0 + 256;
    float* sM0 = sQ1 + 256;
    float* sM1 = sM0 + 256;
    float* sb1 = (float*)(smc + B1OFF);
    float* sz2 = (float*)(smc + Z2OFF);
    float* red = (float*)(smc + REDOFF);
    float* sG  = (float*)(smc + SGOFF);
    const uint32_t smbase = (uint32_t)__cvta_generic_to_shared(smc);

    const int tid  = threadIdx.x;
    const int lane = tid & 31;
    const int wid  = tid >> 5;
    const int g    = lane >> 2;
    const int tg   = lane & 3;
    const int wm   = wid & 3;
    const int wn   = wid >> 2;

    const int bx  = blockIdx.x;
    const int n   = bx >> 5;
    const int ip  = bx & 31;
    const int ni0 = n*64 + ip*2;

    {
        const float2* f2 = (const float2*)(facts + (size_t)n * Ss * Hh);
        #pragma unroll
        for (int e = 0; e < 16; e++) {
            int idx = e*512 + tid;
            int j = idx >> 7, h2 = idx & 127;
            *(float2*)&sf[j*SFP + h2*2] = f2[idx];
        }
        if (tid < 256) {
            sQ0[tid] = questions[(size_t)ni0*256 + tid];
            sQ1[tid] = questions[(size_t)(ni0+1)*256 + tid];
            sM0[tid] = prevM[(size_t)ni0*256 + tid];
            sM1[tid] = prevM[(size_t)(ni0+1)*256 + tid];
            sb1[tid] = z1b[tid];
            sz2[tid] = z2w[tid];
        }
    }

    const int wrow  = tid >> 1;
    const int whalf = tid & 1;

    {
        const char* gh = (const char*)(g_Whi + (size_t)wrow*1024 + whalf*32);
        const char* gl = (const char*)(g_Wlo + (size_t)wrow*1024 + whalf*32);
        uint32_t dh = smbase + WOFF + (uint32_t)(wrow*144 + whalf*64);
        uint32_t dl = dh + WHALF;
        #pragma unroll
        for (int u = 0; u < 4; u++) { cp16(dh + u*16, gh + u*16); cp16(dl + u*16, gl + u*16); }
        asm volatile("cp.async.commit_group;");
        asm volatile("cp.async.wait_group 0;");
    }
    __syncthreads();

    float acc[2][8][4];
    #pragma unroll
    for (int mt = 0; mt < 2; mt++)
        #pragma unroll
        for (int nt = 0; nt < 8; nt++)
            #pragma unroll
            for (int v = 0; v < 4; v++) acc[mt][nt][v] = 0.0f;

    const uint32_t broff = (uint32_t)((wn*64 + ((lane>>4)&1)*8 + (lane&7)) * 144
                                      + ((lane>>3)&1)*16);

    for (int c = 0; c < 16; c++) {
        if (c < 15) {
            const char* gh = (const char*)(g_Whi + (size_t)wrow*1024 + (c+1)*64 + whalf*32);
            const char* gl = (const char*)(g_Wlo + (size_t)wrow*1024 + (c+1)*64 + whalf*32);
            uint32_t dh = smbase + WOFF + (uint32_t)(((c+1)&1)*WBUFSZ)
                        + (uint32_t)(wrow*144 + whalf*64);
            uint32_t dl = dh + WHALF;
            #pragma unroll
            for (int u = 0; u < 4; u++) { cp16(dh + u*16, gh + u*16); cp16(dl + u*16, gl + u*16); }
            asm volatile("cp.async.commit_group;");
        }

        const int  bterm = c >> 2;
        const int  h0    = (c & 3) * 64;
        const bool isabs = (bterm >= 2);
        const uint32_t wbase = smbase + WOFF + (uint32_t)((c&1)*WBUFSZ);

        #pragma unroll
        for (int ks = 0; ks < 4; ks++) {
            const int h = h0 + ks*16;

            uint32_t Ah[2][4], Al[2][4];
            #pragma unroll
            for (int mt = 0; mt < 2; mt++) {
                const int rb   = wm*32 + mt*16 + g;
                const int isel = rb >> 6;
                const float* tv = (bterm & 1) ? (isel ? sM1 : sM0)
                                              : (isel ? sQ1 : sQ0);
                const int j0 = rb & 63;
                const float* fr0 = &sf[j0*SFP + h + tg*2];
                const float* fr1 = fr0 + 8*SFP;
                float2 t0  = *(const float2*)&tv[h + tg*2];
                float2 t1  = *(const float2*)&tv[h + tg*2 + 8];
                float2 fa  = *(const float2*)fr0;
                float2 fA  = *(const float2*)(fr0 + 8);
                float2 fb  = *(const float2*)fr1;
                float2 fB  = *(const float2*)(fr1 + 8);
                float z00, z01, z10, z11, z20, z21, z30, z31;
                if (isabs) {
                    z00 = fabsf(fa.x - t0.x); z01 = fabsf(fa.y - t0.y);
                    z10 = fabsf(fb.x - t0.x); z11 = fabsf(fb.y - t0.y);
                    z20 = fabsf(fA.x - t1.x); z21 = fabsf(fA.y - t1.y);
                    z30 = fabsf(fB.x - t1.x); z31 = fabsf(fB.y - t1.y);
                } else {
                    z00 = fa.x * t0.x; z01 = fa.y * t0.y;
                    z10 = fb.x * t0.x; z11 = fb.y * t0.y;
                    z20 = fA.x * t1.x; z21 = fA.y * t1.y;
                    z30 = fB.x * t1.x; z31 = fB.y * t1.y;
                }
                Ah[mt][0] = split2(z00, z01, Al[mt][0]);
                Ah[mt][1] = split2(z10, z11, Al[mt][1]);
                Ah[mt][2] = split2(z20, z21, Al[mt][2]);
                Ah[mt][3] = split2(z30, z31, Al[mt][3]);
            }

            #pragma unroll
            for (int pass = 0; pass < 3; pass++) {
                const uint32_t* A0 = (pass == 1) ? Al[0] : Ah[0];
                const uint32_t* A1 = (pass == 1) ? Al[1] : Ah[1];
                const uint32_t hoff = (pass == 2) ? (uint32_t)WHALF : 0u;
                #pragma unroll
                for (int p = 0; p < 4; p++) {
                    uint32_t bfr[4];
                    ldm_x4(bfr, wbase + broff + (uint32_t)(p*16*144 + ks*32) + hoff);
                    mma_bf16(acc[0][p*2],   A0, bfr[0], bfr[1]);
                    mma_bf16(acc[1][p*2],   A1, bfr[0], bfr[1]);
                    mma_bf16(acc[0][p*2+1], A0, bfr[2], bfr[3]);
                    mma_bf16(acc[1][p*2+1], A1, bfr[2], bfr[3]);
                }
            }
        }

        if (c < 15) asm volatile("cp.async.wait_group 0;");
        __syncthreads();
    }

    #pragma unroll
    for (int mt = 0; mt < 2; mt++) {
        #pragma unroll
        for (int rh = 0; rh < 2; rh++) {
            const int r = wm*32 + mt*16 + rh*8 + g;
            float s = 0.0f;
            #pragma unroll
            for (int nt = 0; nt < 8; nt++) {
                #pragma unroll
                for (int cc = 0; cc < 2; cc++) {
                    const int a = wn*64 + nt*8 + tg*2 + cc;
                    float x = acc[mt][nt][rh*2 + cc] + sb1[a];
                    s += fast_tanh(x) * sz2[a];
                }
            }
            red[r*16 + wn*4 + tg] = s;
        }
    }
    __syncthreads();
    if (tid < 128) {
        float G = z2b[0];
        #pragma unroll
        for (int u = 0; u < 16; u++) G += red[tid*16 + u];
        sG[tid] = G;
    }
    __syncthreads();
    if (wid < 2) {
        const int row = wid;
        const int dl  = doc_len[n];
        const int b   = ni0 + row;
        float v0 = sG[row*64 + lane];
        float v1 = sG[row*64 + 32 + lane];
        float x0 = (lane      < dl && v0 != 0.0f) ? v0 : -CUDART_INF_F;
        float x1 = (lane + 32 < dl && v1 != 0.0f) ? v1 : -CUDART_INF_F;
        float mx = fmaxf(x0, x1);
        #pragma unroll
        for (int o = 16; o >= 1; o >>= 1)
            mx = fmaxf(mx, __shfl_xor_sync(0xffffffffu, mx, o));
        float e0 = expf(x0 - mx);
        float e1 = expf(x1 - mx);
        float s = e0 + e1;
        #pragma unroll
        for (int o = 16; o >= 1; o >>= 1)
            s += __shfl_xor_sync(0xffffffffu, s, o);
        float inv = 1.0f / s;
        float a0 = e0 * inv, a1 = e1 * inv;
        out_attn[b*64 + lane]      = a0;
        out_attn[b*64 + 32 + lane] = a1;
        g_aT[lane*1024 + b]        = a0;
        g_aT[(lane+32)*1024 + b]   = a1;
    }
}

// ---------------------------------------------------------------------------
// Persistent GRU on TENSOR CORES (bf16-split 3-term mma, same scheme as gate).
// 128 CTAs x 256 threads (8 warps = 4 M-tiles x 2 N-tiles).
// Per step: stage C -> bf16 hi/lo A-tiles; D[64 chains x 64 n] where n
// interleaves Ur (even) / U (odd) rows, so each thread's (c0,c1) pair is
// (Ur.C, U.C) for one output o. R14 two-phase global barrier between steps.
// ---------------------------------------------------------------------------
#define AP 528                  // tile row pitch bytes (256 bf16 + 16B pad)
#define GA_HI 0
#define GA_LO 33792             // 64*528
#define GB_HI 67584
#define GB_LO 101376
#define GRU_SMEM_BYTES 135200

__device__ __forceinline__ void grid_barrier(unsigned expect)
{
    const int tid = threadIdx.x;
    const int bx  = blockIdx.x;
    __syncthreads();
    if (tid == 0) {
        __threadfence();
        asm volatile("st.release.gpu.u32 [%0], %1;"
                     :: "l"(&g_flags[bx]), "r"(expect) : "memory");
    }
    if (bx == 0) {
        if (tid < STEP_CTAS) {
            unsigned v;
            do {
                asm volatile("ld.acquire.gpu.u32 %0, [%1];"
                             : "=r"(v) : "l"(&g_flags[tid]) : "memory");
            } while (v < expect);
        }
        __syncthreads();
        if (tid == 0)
            asm volatile("st.release.gpu.u32 [%0], %1;"
                         :: "l"(&g_gen2), "r"(expect) : "memory");
    } else {
        if (tid == 0) {
            unsigned v;
            do {
                asm volatile("ld.acquire.gpu.u32 %0, [%1];"
                             : "=r"(v) : "l"(&g_gen2) : "memory");
            } while (v < expect);
        }
        __syncthreads();
    }
}

__global__ void __launch_bounds__(256, 1)
gru_persistent(float* __restrict__ Ca, float* __restrict__ Cb,
               const float* __restrict__ Ur, const float* __restrict__ U,
               const float* __restrict__ Ub)
{
    extern __shared__ char smc[];
    const uint32_t smb = (uint32_t)__cvta_generic_to_shared(smc);

    const int bx  = blockIdx.x;
    const int ct  = bx >> 3;                // chain tile (16), 64 chains
    const int ot  = bx & 7;                 // out tile (8), 32 outs
    const int tid = threadIdx.x;
    const int lane = tid & 31;
    const int wid  = tid >> 5;
    const int wm   = wid & 3;               // M 16-tile (chains wm*16..+15)
    const int wn   = wid >> 2;              // N 32-slice (o wn*16..+15)
    const int g    = lane >> 2;
    const int tg   = lane & 3;

    // --- Weights -> bf16 hi/lo B-tiles, rows interleaved: r=2o Ur, r=2o+1 U
    #pragma unroll 4
    for (int u = 0; u < 32; u++) {
        int idx2 = u*256 + tid;             // 8192 float2 over 64 rows
        int r = idx2 >> 7, kk2 = idx2 & 127;
        const float* src = (r & 1) ? U : Ur;
        float2 w = *(const float2*)&src[(size_t)(ot*32 + (r >> 1))*256 + kk2*2];
        uint32_t lo, hi;
        hi = split2(w.x, w.y, lo);
        *(uint32_t*)(smc + GB_HI + r*AP + kk2*4) = hi;
        *(uint32_t*)(smc + GB_LO + r*AP + kk2*4) = lo;
    }
    __syncthreads();

    // ldmatrix base addresses
    // A (row-major m16k16): groups (m0-7,k0),(m8-15,k0),(m0-7,k+16B),(m8-15,k+16B)
    const uint32_t aAddr = smb + GA_HI +
        (uint32_t)((wm*16 + ((lane>>3)&1)*8 + (lane&7))*AP + ((lane>>4)&1)*16);
    // B (n-major rows, col frag): groups (n0-7,k0),(n0-7,k+16B),(n8-15,k0),(n8-15,k+16B)
    const uint32_t bAddr = smb + GB_HI +
        (uint32_t)((wn*32 + ((lane>>4)&1)*8 + (lane&7))*AP + ((lane>>3)&1)*16);

    for (int t = 0; t < 64; t++) {
        const float* Cin  = (t & 1) ? Cb : Ca;
        float*       Cout = (t & 1) ? Ca : Cb;

        // Stage C -> bf16 hi/lo A tiles (coalesced float2 reads, pair-packed)
        #pragma unroll 4
        for (int u = 0; u < 32; u++) {
            int idx2 = u*256 + tid;
            int ch = idx2 >> 7, kk2 = idx2 & 127;
            float2 cv = *(const float2*)&Cin[(size_t)(ct*64 + ch)*256 + kk2*2];
            uint32_t lo, hi;
            hi = split2(cv.x, cv.y, lo);
            *(uint32_t*)(smc + GA_HI + ch*AP + kk2*4) = hi;
            *(uint32_t*)(smc + GA_LO + ch*AP + kk2*4) = lo;
        }
        __syncthreads();

        float acc[4][4];
        #pragma unroll
        for (int q = 0; q < 4; q++)
            #pragma unroll
            for (int v = 0; v < 4; v++) acc[q][v] = 0.0f;

        #pragma unroll 4
        for (int ks = 0; ks < 16; ks++) {
            const uint32_t ko = (uint32_t)(ks*32);
            uint32_t Ah[4], Al[4], B0h[4], B1h[4], B0l[4], B1l[4];
            ldm_x4(Ah,  aAddr + ko);
            ldm_x4(Al,  aAddr + 33792u + ko);
            ldm_x4(B0h, bAddr + ko);
            ldm_x4(B1h, bAddr + 16u*AP + ko);
            ldm_x4(B0l, bAddr + 33792u + ko);
            ldm_x4(B1l, bAddr + 33792u + 16u*AP + ko);
            // pass0: Ahi * Bhi
            mma_bf16(acc[0], Ah, B0h[0], B0h[1]);
            mma_bf16(acc[1], Ah, B0h[2], B0h[3]);
            mma_bf16(acc[2], Ah, B1h[0], B1h[1]);
            mma_bf16(acc[3], Ah, B1h[2], B1h[3]);
            // pass1: Alo * Bhi
            mma_bf16(acc[0], Al, B0h[0], B0h[1]);
            mma_bf16(acc[1], Al, B0h[2], B0h[3]);
            mma_bf16(acc[2], Al, B1h[0], B1h[1]);
            mma_bf16(acc[3], Al, B1h[2], B1h[3]);
            // pass2: Ahi * Blo
            mma_bf16(acc[0], Ah, B0l[0], B0l[1]);
            mma_bf16(acc[1], Ah, B0l[2], B0l[3]);
            mma_bf16(acc[2], Ah, B1l[0], B1l[1]);
            mma_bf16(acc[3], Ah, B1l[2], B1l[3]);
        }

        // Epilogue
        const size_t trow = (size_t)(ct*64 + t) * 256;
        float a1c[4], a2c[4], ubc[4];
        #pragma unroll
        for (int ntl = 0; ntl < 4; ntl++) {
            const int og = ot*32 + wn*16 + ntl*4 + tg;
            a1c[ntl] = g_A1[trow + og];
            a2c[ntl] = g_A2[trow + og];
            ubc[ntl] = Ub[og];
        }
        #pragma unroll
        for (int rh = 0; rh < 2; rh++) {
            const int chain = wm*16 + g + rh*8;
            const int b = ct*64 + chain;
            const float gt = g_aT[t*1024 + b];
            #pragma unroll
            for (int ntl = 0; ntl < 4; ntl++) {
                const int og = ot*32 + wn*16 + ntl*4 + tg;
                const float ci = Cin[(size_t)b*256 + og];
                float r = fast_sigmoid(acc[ntl][rh*2 + 0] + a1c[ntl]);
                float h = fast_tanh(a2c[ntl] + r * (acc[ntl][rh*2 + 1] + ubc[ntl]));
                Cout[(size_t)b*256 + og] = gt*h + (1.0f - gt)*ci;
            }
        }

        if (t < 63) grid_barrier((unsigned)(t + 1));
    }
}

// ---------------------------------------------------------------------------
// next_mem = relu([prevM, C, questions] @ nm_w^T + nm_b).
// ---------------------------------------------------------------------------
__global__ void final_kernel(const float* __restrict__ prevM,
                             const float* __restrict__ questions,
                             const float* __restrict__ C,
                             const float* __restrict__ nmw,
                             const float* __restrict__ nmb,
                             float* __restrict__ out)
{
    __shared__ float sX[64*36];
    __shared__ float sW[64*68];
    const int rt = blockIdx.x;
    const int ot = blockIdx.y;
    const int tid = threadIdx.x;
    const int tr = tid & 7, to = tid >> 3;
    const int r0 = tr*4, o0 = to*2;

    float acc[4][2];
    #pragma unroll
    for (int a = 0; a < 4; a++) { acc[a][0]=acc[a][1]=0.0f; }

    for (int k0 = 0; k0 < 768; k0 += 64) {
        __syncthreads();
        #pragma unroll
        for (int e = 0; e < 8; e++) {
            int idx = e*256 + tid;
            int r = idx >> 6, k = idx & 63;
            int kg = k0 + k;
            const float* src; int off;
            if (kg < 256)      { src = prevM;     off = kg; }
            else if (kg < 512) { src = C;         off = kg - 256; }
            else               { src = questions; off = kg - 512; }
            sX[k*36 + r] = src[(size_t)(rt*32 + r)*256 + off];
        }
        #pragma unroll
        for (int e = 0; e < 16; e++) {
            int idx = e*256 + tid;
            int o = idx >> 6, k = idx & 63;
            sW[k*68 + o] = nmw[(size_t)(ot*64 + o)*768 + k0 + k];
        }
        __syncthreads();
        #pragma unroll 4
        for (int k = 0; k < 64; k++) {
            float4 xv = *(const float4*)&sX[k*36 + r0];
            float2 wv = *(const float2*)&sW[k*68 + o0];
            acc[0][0]+=xv.x*wv.x; acc[0][1]+=xv.x*wv.y;
            acc[1][0]+=xv.y*wv.x; acc[1][1]+=xv.y*wv.y;
            acc[2][0]+=xv.z*wv.x; acc[2][1]+=xv.z*wv.y;
            acc[3][0]+=xv.w*wv.x; acc[3][1]+=xv.w*wv.y;
        }
    }
    #pragma unroll
    for (int rr = 0; rr < 4; rr++)
        #pragma unroll
        for (int oo = 0; oo < 2; oo++) {
            int o = ot*64 + o0 + oo;
            float v = acc[rr][oo] + nmb[o];
            out[(size_t)(rt*32 + r0 + rr)*256 + o] = fmaxf(v, 0.0f);
        }
}

// ---------------------------------------------------------------------------
extern "C" void kernel_launch(void* const* d_in, const int* in_sizes, int n_in,
                              void* d_out, int out_size)
{
    const float* facts     = (const float*)d_in[0];
    const float* prevM     = (const float*)d_in[1];
    const float* questions = (const float*)d_in[2];
    const int*   doc_len   = (const int*)  d_in[3];
    const float* z1w = (const float*)d_in[4];
    const float* z1b = (const float*)d_in[5];
    const float* z2w = (const float*)d_in[6];
    const float* z2b = (const float*)d_in[7];
    const float* Wrw = (const float*)d_in[8];
    const float* Wrb = (const float*)d_in[9];
    const float* Urw = (const float*)d_in[10];
    const float* Urb = (const float*)d_in[11];
    const float* Ww  = (const float*)d_in[12];
    const float* Wb  = (const float*)d_in[13];
    const float* Uw  = (const float*)d_in[14];
    const float* Ub  = (const float*)d_in[15];
    const float* nmw = (const float*)d_in[16];
    const float* nmb = (const float*)d_in[17];

    float* out      = (float*)d_out;              // next_mem first
    float* out_attn = out + NM_ELEMS;             // attn second

    cudaFuncSetAttribute(gate_kernel,
                         cudaFuncAttributeMaxDynamicSharedMemorySize, GATE_SMEM_BYTES);
    cudaFuncSetAttribute(gru_persistent,
                         cudaFuncAttributeMaxDynamicSharedMemorySize, GRU_SMEM_BYTES);

    float *Ca, *Cb;
    cudaGetSymbolAddress((void**)&Ca, g_Ca);
    cudaGetSymbolAddress((void**)&Cb, g_Cb);

    // gru at launch index 3 -> ncu captures the GRU.
    splitw_kernel<<<256, 256>>>(z1w);                                   // 0
    a12_kernel<<<dim3(16, 8), 256>>>(facts, Wrw, Wrb, Urb, Ww, Wb);     // 1
    gate_kernel<<<512, 512, GATE_SMEM_BYTES>>>(facts, prevM, questions, // 2
                                               z1b, z2w, z2b, doc_len, out_attn);
    gru_persistent<<<STEP_CTAS, 256, GRU_SMEM_BYTES>>>(Ca, Cb, Urw, Uw, Ub); // 3
    // After t=63 (odd), final C lives in Ca
    final_kernel<<<dim3(32, 4), 256>>>(prevM, questions, Ca, nmw, nmb, out); // 4
}